// round 8
// baseline (speedup 1.0000x reference)
#include <cuda_runtime.h>
#include <math.h>

// R7 structure (passing @27.1us) with packed f32x2 math in phase 1.
//   Phase 1: 128 ICNN/phi blocks (64 q + 64 k, 64 tokens each) + 16 u-blocks.
//   Phase 2: 64 blocks partial-M.  Phase 3: 128 blocks epilogue.
// Packing: tokens stored transposed [d][t] in smem; fma.rn.f32x2 does 2 MACs/instr.

#define G 144
#define T 512

__device__ float g_f[2][4096];          // [0]=f_q, [1]=g_k
__device__ float g_phi[2][4096*32];     // [0]=phi_q, [1]=phi_k
__device__ float g_u[4096*32];
__device__ float g_Mpart[64][1024];     // [h*8+c][r*32+p]
__device__ unsigned g_mg_ord[8];        // order-encoded maxes (0 == -inf sentinel)
__device__ unsigned g_m2_ord[8*32];
__device__ unsigned long long g_bar;    // monotonic ticket barrier

__device__ __forceinline__ float softplusf(float x){
    return x > 20.0f ? x : __logf(1.0f + __expf(x));
}
__device__ __forceinline__ unsigned ordf(float f){
    unsigned u = __float_as_uint(f);
    return (u & 0x80000000u) ? ~u : (u | 0x80000000u);
}
__device__ __forceinline__ float deco(unsigned k){
    return __uint_as_float((k & 0x80000000u) ? (k ^ 0x80000000u) : ~k);
}

// ---- packed f32x2 helpers ----
__device__ __forceinline__ unsigned long long pk2(float a){
    unsigned long long r;
    asm("mov.b64 %0, {%1, %1};" : "=l"(r) : "f"(a));
    return r;
}
__device__ __forceinline__ unsigned long long pkpair(float lo, float hi){
    unsigned long long r;
    asm("mov.b64 %0, {%1, %2};" : "=l"(r) : "f"(lo), "f"(hi));
    return r;
}
__device__ __forceinline__ void fma2(unsigned long long &acc,
                                     unsigned long long a, unsigned long long b){
    asm("fma.rn.f32x2 %0, %1, %2, %0;" : "+l"(acc) : "l"(a), "l"(b));
}
__device__ __forceinline__ void up2(unsigned long long v, float &lo, float &hi){
    asm("mov.b64 {%0, %1}, %2;" : "=f"(lo), "=f"(hi) : "l"(v));
}

__device__ __forceinline__ void gridbar(){
    __syncthreads();
    if (threadIdx.x == 0){
        __threadfence();
        unsigned long long t = atomicAdd(&g_bar, 1ULL);
        unsigned long long target = (t / G + 1ULL) * G;
        while (*((volatile unsigned long long*)&g_bar) < target) { }
        __threadfence();
    }
    __syncthreads();
}

// ---- shared layout (floats) ----
// ICNN blocks:
#define O_W1   0        // 64x65
#define O_W2   4160     // 64x65
#define O_WHT  8320     // 64x32  [d][r]
#define O_X    10368    // 64x64  [t][d]   (phi)
#define O_XT   14464    // 64x68  [d][t]   (packed ICNN)
#define O_Z1T  18816    // 64x68  [j][t] -> [d][t] for layer 2
#define O_B1   23168
#define O_B2   23232
#define O_RED  23296    // 128
// u-blocks:
#define O_UWVT 0        // 64x32 [d][p]
#define O_SVT  2048     // 64x264 [d][t]
#define O_URED 18944    // 512
#define SMEM_FLOATS 23424

__global__ void __launch_bounds__(T, 1) fused_kernel(
    const float* __restrict__ q,  const float* __restrict__ k,  const float* __restrict__ v,
    const float* __restrict__ sq1, const float* __restrict__ sqb1,
    const float* __restrict__ sq2, const float* __restrict__ sqb2,
    const float* __restrict__ sk1, const float* __restrict__ skb1,
    const float* __restrict__ sk2, const float* __restrict__ skb2,
    const float* __restrict__ Wh, const float* __restrict__ Wv,
    float* __restrict__ y)
{
    extern __shared__ __align__(16) float S[];
    const int tid = threadIdx.x;
    const int bid = blockIdx.x;

    // ============================ PHASE 1 ============================
    if (bid < 128){
        const int which = (bid >= 64);
        const float* x    = which ? k   : q;
        const float* raw1 = which ? sk1 : sq1;
        const float* raw2 = which ? sk2 : sq2;
        const float* b1   = which ? skb1: sqb1;
        const float* b2   = which ? skb2: sqb2;
        const int tb = (which ? bid - 64 : bid) * 64;
        const int h  = tb >> 9;

        float* sW1  = S + O_W1;
        float* sW2  = S + O_W2;
        float* sWhT = S + O_WHT;
        float* sx   = S + O_X;
        float* sxT  = S + O_XT;
        float* sz1T = S + O_Z1T;
        float* sb1  = S + O_B1;
        float* sb2  = S + O_B2;
        float* sred = S + O_RED;

        for (int i = tid; i < 4096; i += T){
            int j = i >> 6, d = i & 63;
            sW1[j*65 + d] = softplusf(raw1[i]);
            sW2[j*65 + d] = softplusf(raw2[i]);
        }
        for (int i = tid; i < 2048; i += T){
            int r = i >> 6, d = i & 63;
            sWhT[d*32 + r] = Wh[i];
        }
        for (int i = tid; i < 4096; i += T){
            int t = i >> 6, d = i & 63;
            float val = x[tb*64 + i];
            sx[i] = val;
            sxT[d*68 + t] = val;
        }
        if (tid < 64){ sb1[tid] = b1[tid]; sb2[tid] = b2[tid]; }
        __syncthreads();

        const int grp = tid >> 6;     // 0..7, 8 tokens each
        const int j   = tid & 63;
        const int t0  = grp * 8;

        // ---- layer 1 (packed) ----
        {
            unsigned long long a0, a1, a2, a3;
            a0 = a1 = a2 = a3 = pk2(sb1[j]);
            #pragma unroll 16
            for (int d = 0; d < 64; d++){
                unsigned long long ww = pk2(sW1[j*65 + d]);
                ulonglong2 xa = *(const ulonglong2*)&sxT[d*68 + t0];
                ulonglong2 xb = *(const ulonglong2*)&sxT[d*68 + t0 + 4];
                fma2(a0, xa.x, ww); fma2(a1, xa.y, ww);
                fma2(a2, xb.x, ww); fma2(a3, xb.y, ww);
            }
            float z[8];
            up2(a0, z[0], z[1]); up2(a1, z[2], z[3]);
            up2(a2, z[4], z[5]); up2(a3, z[6], z[7]);
            #pragma unroll
            for (int i = 0; i < 8; i++) z[i] = softplusf(z[i]);
            ulonglong2 s1, s2;
            s1.x = pkpair(z[0], z[1]); s1.y = pkpair(z[2], z[3]);
            s2.x = pkpair(z[4], z[5]); s2.y = pkpair(z[6], z[7]);
            *(ulonglong2*)&sz1T[j*68 + t0]     = s1;
            *(ulonglong2*)&sz1T[j*68 + t0 + 4] = s2;
        }
        __syncthreads();

        // ---- layer 2 (packed) + reduce over j ----
        {
            unsigned long long a0, a1, a2, a3;
            a0 = a1 = a2 = a3 = pk2(sb2[j]);
            #pragma unroll 16
            for (int d = 0; d < 64; d++){
                unsigned long long ww = pk2(sW2[j*65 + d]);
                ulonglong2 xa = *(const ulonglong2*)&sz1T[d*68 + t0];
                ulonglong2 xb = *(const ulonglong2*)&sz1T[d*68 + t0 + 4];
                fma2(a0, xa.x, ww); fma2(a1, xa.y, ww);
                fma2(a2, xb.x, ww); fma2(a3, xb.y, ww);
            }
            float cv[8];
            up2(a0, cv[0], cv[1]); up2(a1, cv[2], cv[3]);
            up2(a2, cv[4], cv[5]); up2(a3, cv[6], cv[7]);
            #pragma unroll
            for (int i = 0; i < 8; i++){
                float c = softplusf(cv[i]);
                #pragma unroll
                for (int o = 16; o > 0; o >>= 1)
                    c += __shfl_xor_sync(0xffffffffu, c, o);
                cv[i] = c;
            }
            if ((tid & 31) == 0){
                int w = tid >> 5;   // warp 0..15
                #pragma unroll
                for (int i = 0; i < 8; i++) sred[w*8 + i] = cv[i];
            }
        }
        __syncthreads();

        if (tid < 64){
            int t = tid, g2 = t >> 3, i2 = t & 7;
            float f = sred[(g2*2)*8 + i2] + sred[(g2*2 + 1)*8 + i2];
            g_f[which][tb + t] = f;
            if (which){
                float m = f;
                #pragma unroll
                for (int o = 16; o > 0; o >>= 1)
                    m = fmaxf(m, __shfl_xor_sync(0xffffffffu, m, o));
                if ((tid & 31) == 0) atomicMax(&g_mg_ord[h], ordf(m));
            }
        }

        // ---- phi (packed): thread = (token, 4 r's) ----
        {
            const int pt = tid >> 3;         // 0..63
            const int r0 = (tid & 7) * 4;
            unsigned long long p01 = 0ULL, p23 = 0ULL;
            #pragma unroll 8
            for (int d4 = 0; d4 < 64; d4 += 4){
                float4 xq = *(const float4*)&sx[pt*64 + d4];
                {
                    ulonglong2 wp = *(const ulonglong2*)&sWhT[(d4  )*32 + r0];
                    unsigned long long xx = pk2(xq.x);
                    fma2(p01, xx, wp.x); fma2(p23, xx, wp.y);
                }
                {
                    ulonglong2 wp = *(const ulonglong2*)&sWhT[(d4+1)*32 + r0];
                    unsigned long long xx = pk2(xq.y);
                    fma2(p01, xx, wp.x); fma2(p23, xx, wp.y);
                }
                {
                    ulonglong2 wp = *(const ulonglong2*)&sWhT[(d4+2)*32 + r0];
                    unsigned long long xx = pk2(xq.z);
                    fma2(p01, xx, wp.x); fma2(p23, xx, wp.y);
                }
                {
                    ulonglong2 wp = *(const ulonglong2*)&sWhT[(d4+3)*32 + r0];
                    unsigned long long xx = pk2(xq.w);
                    fma2(p01, xx, wp.x); fma2(p23, xx, wp.y);
                }
            }
            float e0, e1, e2, e3;
            up2(p01, e0, e1); up2(p23, e2, e3);
            int base = (tb + pt)*32 + r0;
            g_phi[which][base + 0] = __expf(e0);
            g_phi[which][base + 1] = __expf(e1);
            g_phi[which][base + 2] = __expf(e2);
            g_phi[which][base + 3] = __expf(e3);
        }
    } else {
        // ---- u = v @ Wv.T, blocks 128..143, 256 tokens each (packed) ----
        const int ub = bid - 128;
        const int tb = ub * 256;
        const int h  = tb >> 9;
        float* sWvT = S + O_UWVT;      // [d][p]
        float* svT  = S + O_SVT;       // [d][t] stride 264
        float* sred = S + O_URED;

        for (int i = tid; i < 2048; i += T){
            int r = i >> 6, d = i & 63;
            sWvT[d*32 + r] = Wv[i];
        }
        for (int i = tid; i < 16384; i += T){
            int t = i >> 6, d = i & 63;
            svT[d*264 + t] = v[tb*64 + i];
        }
        __syncthreads();

        const int p = tid & 31, tr = tid >> 5;     // 16 tr, 16 tokens each
        const int t0a = tr*16, t0b = tr*16 + 8;
        unsigned long long a0=0,a1=0,a2=0,a3=0,a4=0,a5=0,a6=0,a7=0;
        #pragma unroll 8
        for (int d = 0; d < 64; d++){
            unsigned long long ww = pk2(sWvT[d*32 + p]);
            const float* row = &svT[d*264];
            ulonglong2 xa = *(const ulonglong2*)&row[t0a];
            ulonglong2 xb = *(const ulonglong2*)&row[t0a + 4];
            ulonglong2 xc = *(const ulonglong2*)&row[t0b];
            ulonglong2 xd = *(const ulonglong2*)&row[t0b + 4];
            fma2(a0, xa.x, ww); fma2(a1, xa.y, ww);
            fma2(a2, xb.x, ww); fma2(a3, xb.y, ww);
            fma2(a4, xc.x, ww); fma2(a5, xc.y, ww);
            fma2(a6, xd.x, ww); fma2(a7, xd.y, ww);
        }
        float uv[16];
        up2(a0, uv[0], uv[1]);  up2(a1, uv[2], uv[3]);
        up2(a2, uv[4], uv[5]);  up2(a3, uv[6], uv[7]);
        up2(a4, uv[8], uv[9]);  up2(a5, uv[10], uv[11]);
        up2(a6, uv[12], uv[13]); up2(a7, uv[14], uv[15]);
        float mx = -1e30f;
        #pragma unroll
        for (int i = 0; i < 16; i++){
            g_u[(tb + t0a + i)*32 + p] = uv[i];
            mx = fmaxf(mx, uv[i]);
        }
        sred[tr*32 + p] = mx;
        __syncthreads();
        if (tid < 32){
            float m = sred[tid];
            #pragma unroll
            for (int rr = 1; rr < 16; rr++) m = fmaxf(m, sred[rr*32 + tid]);
            atomicMax(&g_m2_ord[h*32 + tid], ordf(m));
        }
    }

    gridbar();

    // ============================ PHASE 2 ============================
    if (bid < 64){
        const int h = bid >> 3, c = bid & 7;
        const int gtb = h*512 + c*64;
        float* seg = S;          // 64
        float* sm2 = S + 64;     // 32
        float* sw  = S + 96;     // 64x32
        float* spk = S + 96 + 2048; // 64x32

        float mg = deco(__ldcg(&g_mg_ord[h]));
        if (tid < 32) sm2[tid] = deco(__ldcg(&g_m2_ord[h*32 + tid]));
        if (tid >= 64 && tid < 128) seg[tid - 64] = __expf(__ldcg(&g_f[1][gtb + tid - 64]) - mg);
        __syncthreads();

        for (int i = tid; i < 2048; i += T){
            int t = i >> 5, p = i & 31;
            sw[i]  = seg[t] * __expf(__ldcg(&g_u[(gtb + t)*32 + p]) - sm2[p]);
            spk[i] = __ldcg(&g_phi[1][(gtb + t)*32 + p]);
        }
        __syncthreads();

        for (int o = tid; o < 1024; o += T){
            int r = o >> 5, p = o & 31;
            float a = 0.f;
            #pragma unroll
            for (int t = 0; t < 64; t++) a += spk[t*32 + r] * sw[t*32 + p];
            g_Mpart[bid][o] = a;
        }
    }

    gridbar();

    // ============================ PHASE 3 ============================
    if (bid < 128){
        const int h = bid >> 4, sc = bid & 15;
        const int s0 = h*512 + sc*32;
        float* sM  = S;          // 32x32
        float* spq = S + 1024;   // 32x32
        float* sm2 = S + 2048;   // 32
        float* sf  = S + 2080;   // 32

        for (int o = tid; o < 1024; o += T){
            float a = 0.f;
            #pragma unroll
            for (int c = 0; c < 8; c++) a += __ldcg(&g_Mpart[h*8 + c][o]);
            sM[o] = a;
        }
        for (int i = tid; i < 1024; i += T) spq[i] = __ldcg(&g_phi[0][s0*32 + i]);
        if (tid < 32){
            sm2[tid] = deco(__ldcg(&g_m2_ord[h*32 + tid]));
            sf[tid]  = __ldcg(&g_f[0][s0 + tid]);
        }
        float mg = deco(__ldcg(&g_mg_ord[h]));
        __syncthreads();

        const float LOGS = 6.2383246250395077847f; // log(512)
        for (int o = tid; o < 1024; o += T){
            int s = o >> 5, p = o & 31;
            float a = 0.f;
            #pragma unroll
            for (int r = 0; r < 32; r++) a += spq[s*32 + r] * sM[r*32 + p];
            y[(s0 + s)*32 + p] = sf[s] + mg + sm2[p] - LOGS + __logf(a);
        }
    }
}

extern "C" void kernel_launch(void* const* d_in, const int* in_sizes, int n_in,
                              void* d_out, int out_size){
    const float* q    = (const float*)d_in[0];
    const float* k    = (const float*)d_in[1];
    const float* v    = (const float*)d_in[2];
    const float* sq1  = (const float*)d_in[3];
    const float* sqb1 = (const float*)d_in[4];
    const float* sq2  = (const float*)d_in[5];
    const float* sqb2 = (const float*)d_in[6];
    const float* sk1  = (const float*)d_in[7];
    const float* skb1 = (const float*)d_in[8];
    const float* sk2  = (const float*)d_in[9];
    const float* skb2 = (const float*)d_in[10];
    const float* Wh   = (const float*)d_in[11];
    const float* Wv   = (const float*)d_in[12];
    float* y = (float*)d_out;

    cudaFuncSetAttribute(fused_kernel, cudaFuncAttributeMaxDynamicSharedMemorySize,
                         SMEM_FLOATS * (int)sizeof(float));
    fused_kernel<<<G, T, SMEM_FLOATS * sizeof(float)>>>(
        q, k, v, sq1, sqb1, sq2, sqb2, sk1, skb1, sk2, skb2, Wh, Wv, y);
}

// round 9
// speedup vs baseline: 1.0024x; 1.0024x over previous
#include <cuda_runtime.h>
#include <math.h>

// R8 structure (passing @27.1us), re-parallelized at T=1024 (32 warps/SM):
//   Phase 1: 128 ICNN/phi blocks (64 tokens each; 16 grp x 64 j, 4 tok/thread)
//            + 16 u-blocks (256 tokens; 32 tr x 32 p, 8 tok/thread)
//   Phase 2: 64 blocks partial-M (1 elem/thread).  Phase 3: 128 blocks epilogue.
// f32x2 packed math throughout phase 1.

#define G 144
#define T 1024

__device__ float g_f[2][4096];
__device__ float g_phi[2][4096*32];
__device__ float g_u[4096*32];
__device__ float g_Mpart[64][1024];
__device__ unsigned g_mg_ord[8];
__device__ unsigned g_m2_ord[8*32];
__device__ unsigned long long g_bar;

__device__ __forceinline__ float softplusf(float x){
    return x > 20.0f ? x : __logf(1.0f + __expf(x));
}
__device__ __forceinline__ unsigned ordf(float f){
    unsigned u = __float_as_uint(f);
    return (u & 0x80000000u) ? ~u : (u | 0x80000000u);
}
__device__ __forceinline__ float deco(unsigned k){
    return __uint_as_float((k & 0x80000000u) ? (k ^ 0x80000000u) : ~k);
}

__device__ __forceinline__ unsigned long long pk2(float a){
    unsigned long long r;
    asm("mov.b64 %0, {%1, %1};" : "=l"(r) : "f"(a));
    return r;
}
__device__ __forceinline__ unsigned long long pkpair(float lo, float hi){
    unsigned long long r;
    asm("mov.b64 %0, {%1, %2};" : "=l"(r) : "f"(lo), "f"(hi));
    return r;
}
__device__ __forceinline__ void fma2(unsigned long long &acc,
                                     unsigned long long a, unsigned long long b){
    asm("fma.rn.f32x2 %0, %1, %2, %0;" : "+l"(acc) : "l"(a), "l"(b));
}
__device__ __forceinline__ void up2(unsigned long long v, float &lo, float &hi){
    asm("mov.b64 {%0, %1}, %2;" : "=f"(lo), "=f"(hi) : "l"(v));
}

__device__ __forceinline__ void gridbar(){
    __syncthreads();
    if (threadIdx.x == 0){
        __threadfence();
        unsigned long long t = atomicAdd(&g_bar, 1ULL);
        unsigned long long target = (t / G + 1ULL) * G;
        while (*((volatile unsigned long long*)&g_bar) < target) { }
        __threadfence();
    }
    __syncthreads();
}

// ---- shared layout (floats) ----
// ICNN blocks:
#define O_W1   0        // 64x65
#define O_W2   4160     // 64x65
#define O_WHT  8320     // 64x32  [d][r]
#define O_X    10368    // 64x64  [t][d]
#define O_XT   14464    // 64x68  [d][t]
#define O_Z1T  18816    // 64x68
#define O_B1   23168
#define O_B2   23232
#define O_RED  23296    // 128
// u-blocks:
#define O_UWVT 0        // 64x32 [d][p]
#define O_SVT  2048     // 64x264 [d][t]
#define O_URED 18944    // 1024
#define SMEM_FLOATS 23424

__global__ void __launch_bounds__(T, 1) fused_kernel(
    const float* __restrict__ q,  const float* __restrict__ k,  const float* __restrict__ v,
    const float* __restrict__ sq1, const float* __restrict__ sqb1,
    const float* __restrict__ sq2, const float* __restrict__ sqb2,
    const float* __restrict__ sk1, const float* __restrict__ skb1,
    const float* __restrict__ sk2, const float* __restrict__ skb2,
    const float* __restrict__ Wh, const float* __restrict__ Wv,
    float* __restrict__ y)
{
    extern __shared__ __align__(16) float S[];
    const int tid = threadIdx.x;
    const int bid = blockIdx.x;

    // ============================ PHASE 1 ============================
    if (bid < 128){
        const int which = (bid >= 64);
        const float* x    = which ? k   : q;
        const float* raw1 = which ? sk1 : sq1;
        const float* raw2 = which ? sk2 : sq2;
        const float* b1   = which ? skb1: sqb1;
        const float* b2   = which ? skb2: sqb2;
        const int tb = (which ? bid - 64 : bid) * 64;
        const int h  = tb >> 9;

        float* sW1  = S + O_W1;
        float* sW2  = S + O_W2;
        float* sWhT = S + O_WHT;
        float* sx   = S + O_X;
        float* sxT  = S + O_XT;
        float* sz1T = S + O_Z1T;
        float* sb1  = S + O_B1;
        float* sb2  = S + O_B2;
        float* sred = S + O_RED;

        for (int i = tid; i < 4096; i += T){
            int j = i >> 6, d = i & 63;
            sW1[j*65 + d] = softplusf(raw1[i]);
            sW2[j*65 + d] = softplusf(raw2[i]);
        }
        for (int i = tid; i < 2048; i += T){
            int r = i >> 6, d = i & 63;
            sWhT[d*32 + r] = Wh[i];
        }
        for (int i = tid; i < 4096; i += T){
            int t = i >> 6, d = i & 63;
            float val = x[tb*64 + i];
            sx[i] = val;
            sxT[d*68 + t] = val;
        }
        if (tid < 64){ sb1[tid] = b1[tid]; sb2[tid] = b2[tid]; }
        __syncthreads();

        const int grp = tid >> 6;     // 0..15, 4 tokens each
        const int j   = tid & 63;
        const int t0  = grp * 4;

        // ---- layer 1 (packed, 4 tokens/thread) ----
        {
            unsigned long long a0, a1;
            a0 = a1 = pk2(sb1[j]);
            #pragma unroll 16
            for (int d = 0; d < 64; d++){
                unsigned long long ww = pk2(sW1[j*65 + d]);
                ulonglong2 xa = *(const ulonglong2*)&sxT[d*68 + t0];
                fma2(a0, xa.x, ww); fma2(a1, xa.y, ww);
            }
            float z[4];
            up2(a0, z[0], z[1]); up2(a1, z[2], z[3]);
            #pragma unroll
            for (int i = 0; i < 4; i++) z[i] = softplusf(z[i]);
            ulonglong2 s1;
            s1.x = pkpair(z[0], z[1]); s1.y = pkpair(z[2], z[3]);
            *(ulonglong2*)&sz1T[j*68 + t0] = s1;
        }
        __syncthreads();

        // ---- layer 2 (packed) + reduce over j ----
        {
            unsigned long long a0, a1;
            a0 = a1 = pk2(sb2[j]);
            #pragma unroll 16
            for (int d = 0; d < 64; d++){
                unsigned long long ww = pk2(sW2[j*65 + d]);
                ulonglong2 xa = *(const ulonglong2*)&sz1T[d*68 + t0];
                fma2(a0, xa.x, ww); fma2(a1, xa.y, ww);
            }
            float cv[4];
            up2(a0, cv[0], cv[1]); up2(a1, cv[2], cv[3]);
            #pragma unroll
            for (int i = 0; i < 4; i++){
                float c = softplusf(cv[i]);
                #pragma unroll
                for (int o = 16; o > 0; o >>= 1)
                    c += __shfl_xor_sync(0xffffffffu, c, o);
                cv[i] = c;
            }
            if ((tid & 31) == 0){
                int w = tid >> 5;   // warp 0..31
                #pragma unroll
                for (int i = 0; i < 4; i++) sred[w*4 + i] = cv[i];
            }
        }
        __syncthreads();

        if (tid < 64){
            int t = tid, g2 = t >> 2, i2 = t & 3;     // grp g2 covered by warps 2g2, 2g2+1
            float f = sred[(g2*2)*4 + i2] + sred[(g2*2 + 1)*4 + i2];
            g_f[which][tb + t] = f;
            if (which){
                float m = f;
                #pragma unroll
                for (int o = 16; o > 0; o >>= 1)
                    m = fmaxf(m, __shfl_xor_sync(0xffffffffu, m, o));
                if ((tid & 31) == 0) atomicMax(&g_mg_ord[h], ordf(m));
            }
        }

        // ---- phi (packed): thread = (token, 2 r's) ----
        {
            const int pt = tid >> 4;          // 0..63
            const int r0 = (tid & 15) * 2;
            unsigned long long p01 = 0ULL;
            #pragma unroll 8
            for (int d4 = 0; d4 < 64; d4 += 4){
                float4 xq = *(const float4*)&sx[pt*64 + d4];
                {
                    unsigned long long wp = *(const unsigned long long*)&sWhT[(d4  )*32 + r0];
                    fma2(p01, pk2(xq.x), wp);
                }
                {
                    unsigned long long wp = *(const unsigned long long*)&sWhT[(d4+1)*32 + r0];
                    fma2(p01, pk2(xq.y), wp);
                }
                {
                    unsigned long long wp = *(const unsigned long long*)&sWhT[(d4+2)*32 + r0];
                    fma2(p01, pk2(xq.z), wp);
                }
                {
                    unsigned long long wp = *(const unsigned long long*)&sWhT[(d4+3)*32 + r0];
                    fma2(p01, pk2(xq.w), wp);
                }
            }
            float e0, e1;
            up2(p01, e0, e1);
            int base = (tb + pt)*32 + r0;
            g_phi[which][base + 0] = __expf(e0);
            g_phi[which][base + 1] = __expf(e1);
        }
    } else {
        // ---- u = v @ Wv.T, blocks 128..143, 256 tokens each ----
        const int ub = bid - 128;
        const int tb = ub * 256;
        const int h  = tb >> 9;
        float* sWvT = S + O_UWVT;
        float* svT  = S + O_SVT;       // [d][t] stride 264
        float* sred = S + O_URED;      // 32x32

        for (int i = tid; i < 2048; i += T){
            int r = i >> 6, d = i & 63;
            sWvT[d*32 + r] = Wv[i];
        }
        for (int i = tid; i < 16384; i += T){
            int t = i >> 6, d = i & 63;
            svT[d*264 + t] = v[tb*64 + i];
        }
        __syncthreads();

        const int p = tid & 31, tr = tid >> 5;   // 32 tr, 8 tokens each
        const int t0 = tr*8;
        unsigned long long a0=0,a1=0,a2=0,a3=0;
        #pragma unroll 8
        for (int d = 0; d < 64; d++){
            unsigned long long ww = pk2(sWvT[d*32 + p]);
            const float* row = &svT[d*264];
            ulonglong2 xa = *(const ulonglong2*)&row[t0];
            ulonglong2 xb = *(const ulonglong2*)&row[t0 + 4];
            fma2(a0, xa.x, ww); fma2(a1, xa.y, ww);
            fma2(a2, xb.x, ww); fma2(a3, xb.y, ww);
        }
        float uv[8];
        up2(a0, uv[0], uv[1]); up2(a1, uv[2], uv[3]);
        up2(a2, uv[4], uv[5]); up2(a3, uv[6], uv[7]);
        float mx = -1e30f;
        #pragma unroll
        for (int i = 0; i < 8; i++){
            g_u[(tb + t0 + i)*32 + p] = uv[i];
            mx = fmaxf(mx, uv[i]);
        }
        sred[tr*32 + p] = mx;
        __syncthreads();
        if (tid < 32){
            float m = sred[tid];
            #pragma unroll
            for (int rr = 1; rr < 32; rr++) m = fmaxf(m, sred[rr*32 + tid]);
            atomicMax(&g_m2_ord[h*32 + tid], ordf(m));
        }
    }

    gridbar();

    // ============================ PHASE 2 ============================
    if (bid < 64){
        const int h = bid >> 3, c = bid & 7;
        const int gtb = h*512 + c*64;
        float* seg = S;          // 64
        float* sm2 = S + 64;     // 32
        float* sw  = S + 96;     // 64x32
        float* spk = S + 96 + 2048; // 64x32

        float mg = deco(__ldcg(&g_mg_ord[h]));
        if (tid < 32) sm2[tid] = deco(__ldcg(&g_m2_ord[h*32 + tid]));
        if (tid >= 64 && tid < 128) seg[tid - 64] = __expf(__ldcg(&g_f[1][gtb + tid - 64]) - mg);
        __syncthreads();

        for (int i = tid; i < 2048; i += T){
            int t = i >> 5, p = i & 31;
            sw[i]  = seg[t] * __expf(__ldcg(&g_u[(gtb + t)*32 + p]) - sm2[p]);
            spk[i] = __ldcg(&g_phi[1][(gtb + t)*32 + p]);
        }
        __syncthreads();

        if (tid < 1024){
            int r = tid >> 5, p = tid & 31;
            float a = 0.f;
            #pragma unroll
            for (int t = 0; t < 64; t++) a += spk[t*32 + r] * sw[t*32 + p];
            g_Mpart[bid][tid] = a;
        }
    }

    gridbar();

    // ============================ PHASE 3 ============================
    if (bid < 128){
        const int h = bid >> 4, sc = bid & 15;
        const int s0 = h*512 + sc*32;
        float* sM  = S;          // 32x32
        float* spq = S + 1024;   // 32x32
        float* sm2 = S + 2048;   // 32
        float* sf  = S + 2080;   // 32

        if (tid < 1024){
            float a = 0.f;
            #pragma unroll
            for (int c = 0; c < 8; c++) a += __ldcg(&g_Mpart[h*8 + c][tid]);
            sM[tid] = a;
            spq[tid] = __ldcg(&g_phi[0][s0*32 + tid]);
        }
        if (tid < 32){
            sm2[tid] = deco(__ldcg(&g_m2_ord[h*32 + tid]));
            sf[tid]  = __ldcg(&g_f[0][s0 + tid]);
        }
        float mg = deco(__ldcg(&g_mg_ord[h]));
        __syncthreads();

        const float LOGS = 6.2383246250395077847f; // log(512)
        if (tid < 1024){
            int s = tid >> 5, p = tid & 31;
            float a = 0.f;
            #pragma unroll
            for (int r = 0; r < 32; r++) a += spq[s*32 + r] * sM[r*32 + p];
            y[(s0 + s)*32 + p] = sf[s] + mg + sm2[p] - LOGS + __logf(a);
        }
    }
}

extern "C" void kernel_launch(void* const* d_in, const int* in_sizes, int n_in,
                              void* d_out, int out_size){
    const float* q    = (const float*)d_in[0];
    const float* k    = (const float*)d_in[1];
    const float* v    = (const float*)d_in[2];
    const float* sq1  = (const float*)d_in[3];
    const float* sqb1 = (const float*)d_in[4];
    const float* sq2  = (const float*)d_in[5];
    const float* sqb2 = (const float*)d_in[6];
    const float* sk1  = (const float*)d_in[7];
    const float* skb1 = (const float*)d_in[8];
    const float* sk2  = (const float*)d_in[9];
    const float* skb2 = (const float*)d_in[10];
    const float* Wh   = (const float*)d_in[11];
    const float* Wv   = (const float*)d_in[12];
    float* y = (float*)d_out;

    cudaFuncSetAttribute(fused_kernel, cudaFuncAttributeMaxDynamicSharedMemorySize,
                         SMEM_FLOATS * (int)sizeof(float));
    fused_kernel<<<G, T, SMEM_FLOATS * sizeof(float)>>>(
        q, k, v, sq1, sqb1, sq2, sqb2, sk1, skb1, sk2, skb2, Wh, Wv, y);
}